// round 6
// baseline (speedup 1.0000x reference)
#include <cuda_runtime.h>
#include <mma.h>
#include <math.h>
using namespace nvcuda;

#define BATCH 32
#define NSEGC 8
#define SLEN  128
#define TTOT  1024
#define KTAG  16
#define MROWS 32768

// ---------------- device scratch ----------------
__device__ float g_G1 [(size_t)MROWS * 1024];   // stage1 x-gates (packed rows)
__device__ float g_P2 [(size_t)MROWS * 256];    // packed lstm2 input (= packed stage1 out)
__device__ float g_G2 [(size_t)MROWS * 1024];   // stage2 x-gates (packed rows)
__device__ float g_OUT2[(size_t)MROWS * 256];   // stage2 outputs (packed)
__device__ float g_EM [(size_t)MROWS * KTAG];   // emissions (packed)
__device__ float g_Whi[1024 * 256];             // tf32-hi of [Wf;Wb]
__device__ float g_Wlo[1024 * 256];             // tf32-lo of [Wf;Wb]
__device__ float g_bias[1024];                  // bih+bhh, f then b
__device__ int   g_segoff[257];
__device__ int   g_tokmap[MROWS];
__device__ float g_Hf[2][BATCH][128];
__device__ float g_Cf[2][BATCH][128];
__device__ uint4 g_HIST4[(size_t)(TTOT - 1) * BATCH];

// ---------------- helpers ----------------
__device__ __forceinline__ float f2tf(float x)
{
    float r;
    asm("cvt.rna.tf32.f32 %0, %1;" : "=f"(r) : "f"(x));
    return r;
}
__device__ __forceinline__ float sig_fast(float x)
{
    return __fdividef(1.0f, 1.0f + __expf(-x));
}
__device__ __forceinline__ float tanh_fast(float x)
{
    return 1.0f - 2.0f * __fdividef(1.0f, 1.0f + __expf(2.0f * x));
}

// ---------------- offsets: warp scan of 256 lengths (FIXED scan) ----------------
__global__ void k_offsets(const int* __restrict__ lengths)
{
    int lane = threadIdx.x;
    int v[8], s = 0;
#pragma unroll
    for (int i = 0; i < 8; i++) { v[i] = lengths[lane * 8 + i]; s += v[i]; }
    int inc = s;
#pragma unroll
    for (int d = 1; d < 32; d <<= 1) {
        int o = __shfl_up_sync(0xFFFFFFFFu, inc, d);
        if (lane >= d) inc += o;
    }
    int run = inc - s;                    // exclusive prefix of lane sums
#pragma unroll
    for (int i = 0; i < 8; i++) { g_segoff[lane * 8 + i] = run; run += v[i]; }
    if (lane == 31) g_segoff[256] = run;
}

__global__ void k_rowmap(const int* __restrict__ texts, const int* __restrict__ lengths)
{
    int bs = blockIdx.x;
    int len = lengths[bs];
    int off = g_segoff[bs];
    int s = threadIdx.x;
    if (s < len) g_tokmap[off + s] = texts[bs * 128 + s];
}

// ---------------- weight preconversion: [Wf;Wb] -> tf32 hi/lo, bias sum ----------------
__global__ void k_convW(const float* __restrict__ Wf, const float* __restrict__ Wb,
                        const float* __restrict__ b1f, const float* __restrict__ b2f,
                        const float* __restrict__ b1b, const float* __restrict__ b2b)
{
    int idx = blockIdx.x * 256 + threadIdx.x;
#pragma unroll
    for (int e = 0; e < 4; e++) {
        int i = idx * 4 + e;
        int n = i >> 8, k = i & 255;
        float v = (n < 512) ? Wf[n * 256 + k] : Wb[(n - 512) * 256 + k];
        float hi = f2tf(v);
        g_Whi[i] = hi;
        g_Wlo[i] = f2tf(v - hi);
    }
    if (idx < 1024) {
        g_bias[idx] = (idx < 512) ? (b1f[idx] + b2f[idx])
                                  : (b1b[idx - 512] + b2b[idx - 512]);
    }
}

// ---------------- 3xTF32 tensor-core GEMM, preconverted weights ----------------
#define SMEM_G3 ((4 * 128 * 40 + 16 * 136) * 4)

template<int GATHER>
__global__ __launch_bounds__(256, 2) void k_gemm3(
    const float* __restrict__ A, float* __restrict__ C)
{
    int total = g_segoff[256];
    int bm = blockIdx.x * 128;
    if (bm >= total) return;
    int bn = blockIdx.y * 128;

    extern __shared__ float sm[];
    float* Ash = sm;                       // [128][40]
    float* Asl = sm + 128 * 40;
    float* Bsh = sm + 2 * 128 * 40;
    float* Bsl = sm + 3 * 128 * 40;
    float* bias_s = sm + 4 * 128 * 40;     // [16][136]

    int tid = threadIdx.x;
    for (int i = tid; i < 16 * 128; i += 256) {
        int r = i >> 7, c = i & 127;
        bias_s[r * 136 + c] = g_bias[bn + c];
    }

    int r0 = tid >> 3;
    int f4 = (tid & 7) * 4;
    const float* arow[4];
#pragma unroll
    for (int p = 0; p < 4; p++) {
        int pr = bm + r0 + 32 * p;
        if (GATHER) {
            int tok = (pr < total) ? g_tokmap[pr] : 0;
            arow[p] = A + (size_t)tok * 256;
        } else {
            arow[p] = A + (size_t)pr * 256;
        }
    }
    const float* whrow = g_Whi + (size_t)(bn + r0) * 256;
    const float* wlrow = g_Wlo + (size_t)(bn + r0) * 256;

    int wid = tid >> 5;
    int lm = (wid & 3) * 32;
    int ln = (wid >> 2) * 64;

    wmma::fragment<wmma::accumulator, 16, 16, 8, float> acc[2][4];
    __syncthreads();
#pragma unroll
    for (int mi = 0; mi < 2; mi++)
#pragma unroll
        for (int ni = 0; ni < 4; ni++)
            wmma::load_matrix_sync(acc[mi][ni], bias_s + ln + ni * 16, 136,
                                   wmma::mem_row_major);

    for (int k0 = 0; k0 < 256; k0 += 32) {
        float4 av[4], bh4[4], bl4[4];
#pragma unroll
        for (int p = 0; p < 4; p++) {
            av[p]  = *(const float4*)(arow[p] + k0 + f4);
            bh4[p] = *(const float4*)(whrow + (size_t)p * 32 * 256 + k0 + f4);
            bl4[p] = *(const float4*)(wlrow + (size_t)p * 32 * 256 + k0 + f4);
        }
        __syncthreads();
#pragma unroll
        for (int p = 0; p < 4; p++) {
            int row = (r0 + 32 * p) * 40 + f4;
            float h0 = f2tf(av[p].x), h1 = f2tf(av[p].y),
                  h2 = f2tf(av[p].z), h3 = f2tf(av[p].w);
            *(float4*)&Ash[row] = make_float4(h0, h1, h2, h3);
            *(float4*)&Asl[row] = make_float4(f2tf(av[p].x - h0), f2tf(av[p].y - h1),
                                              f2tf(av[p].z - h2), f2tf(av[p].w - h3));
            *(float4*)&Bsh[row] = bh4[p];
            *(float4*)&Bsl[row] = bl4[p];
        }
        __syncthreads();
#pragma unroll
        for (int ks = 0; ks < 4; ks++) {
            wmma::fragment<wmma::matrix_a, 16, 16, 8, wmma::precision::tf32,
                           wmma::row_major> ah[2], al[2];
#pragma unroll
            for (int mi = 0; mi < 2; mi++) {
                wmma::load_matrix_sync(ah[mi], Ash + (lm + mi * 16) * 40 + ks * 8, 40);
                wmma::load_matrix_sync(al[mi], Asl + (lm + mi * 16) * 40 + ks * 8, 40);
            }
#pragma unroll
            for (int ni = 0; ni < 4; ni++) {
                wmma::fragment<wmma::matrix_b, 16, 16, 8, wmma::precision::tf32,
                               wmma::col_major> bh, bl;
                wmma::load_matrix_sync(bh, Bsh + (ln + ni * 16) * 40 + ks * 8, 40);
                wmma::load_matrix_sync(bl, Bsl + (ln + ni * 16) * 40 + ks * 8, 40);
#pragma unroll
                for (int mi = 0; mi < 2; mi++) {
                    wmma::mma_sync(acc[mi][ni], ah[mi], bl, acc[mi][ni]);
                    wmma::mma_sync(acc[mi][ni], al[mi], bh, acc[mi][ni]);
                    wmma::mma_sync(acc[mi][ni], ah[mi], bh, acc[mi][ni]);
                }
            }
        }
    }
#pragma unroll
    for (int mi = 0; mi < 2; mi++)
#pragma unroll
        for (int ni = 0; ni < 4; ni++)
            wmma::store_matrix_sync(
                C + (size_t)(bm + lm + mi * 16) * 1024 + bn + ln + ni * 16,
                acc[mi][ni], 1024, wmma::mem_row_major);
}

// ---------------- paired LSTM recurrent core (2 sequences / CTA, same Whh) --------
#define SMEM_LSTMP ((512 * 68 + 256 + 1024) * 4)

__device__ __forceinline__ void lstm_pair_run(
    const float* __restrict__ Whh,
    const float* __restrict__ Gb0, const float* __restrict__ Gb1,
    float* __restrict__ Ob0, float* __restrict__ Ob1,
    int len0, int len1, int dir, int t,
    float* ws, float* hs0, float* hs1, float* ga0, float* ga1,
    float c_init, int wf0, int wf1, int b0, int b1)
{
    const float* wr = Whh + t * 128;
    float w[64];
#pragma unroll
    for (int q = 0; q < 16; q++) {
        float4 v = *(const float4*)(wr + q * 4);
        w[4*q]=v.x; w[4*q+1]=v.y; w[4*q+2]=v.z; w[4*q+3]=v.w;
    }
    float* wsr = ws + t * 68;
#pragma unroll
    for (int q = 0; q < 16; q++)
        *(float4*)(wsr + 4 * q) = *(const float4*)(wr + 64 + 4 * q);

    float c = c_init;
    __syncthreads();

    int nsteps = max(len0, len1);
    int stp = dir ? -1 : 1;
    int s0 = dir ? (len0 - 1) : 0;
    int s1 = dir ? (len1 - 1) : 0;
    float xg0 = Gb0[(size_t)s0 * 1024];
    float xg1 = Gb1[(size_t)s1 * 1024];
    bool isg = ((t >> 7) == 2);

    for (int it = 0; it < nsteps; it++) {
        int it1 = it + 1;
        float xg0n = 0.f, xg1n = 0.f;
        if (it1 < len0) xg0n = Gb0[(size_t)(s0 + stp) * 1024];
        if (it1 < len1) xg1n = Gb1[(size_t)(s1 + stp) * 1024];

        float a0a = xg0, a0b = 0.f, a1a = xg1, a1b = 0.f;
        const float4* h40 = (const float4*)hs0;
        const float4* h41 = (const float4*)hs1;
#pragma unroll
        for (int q = 0; q < 16; q++) {
            float4 u = h40[q], v = h41[q];
            a0a = fmaf(w[4*q  ], u.x, a0a); a0b = fmaf(w[4*q+1], u.y, a0b);
            a0a = fmaf(w[4*q+2], u.z, a0a); a0b = fmaf(w[4*q+3], u.w, a0b);
            a1a = fmaf(w[4*q  ], v.x, a1a); a1b = fmaf(w[4*q+1], v.y, a1b);
            a1a = fmaf(w[4*q+2], v.z, a1a); a1b = fmaf(w[4*q+3], v.w, a1b);
        }
#pragma unroll
        for (int q = 0; q < 16; q++) {
            float4 wv = *(const float4*)(wsr + 4 * q);
            float4 u = h40[16 + q], v = h41[16 + q];
            a0a = fmaf(wv.x, u.x, a0a); a0b = fmaf(wv.y, u.y, a0b);
            a0a = fmaf(wv.z, u.z, a0a); a0b = fmaf(wv.w, u.w, a0b);
            a1a = fmaf(wv.x, v.x, a1a); a1b = fmaf(wv.y, v.y, a1b);
            a1a = fmaf(wv.z, v.z, a1a); a1b = fmaf(wv.w, v.w, a1b);
        }
        float acc0 = a0a + a0b, acc1 = a1a + a1b;
        ga0[t] = isg ? tanh_fast(acc0) : sig_fast(acc0);
        ga1[t] = isg ? tanh_fast(acc1) : sig_fast(acc1);
        __syncthreads();
        if (t < 256) {
            int q = t >> 7, j = t & 127;
            int lenq = q ? len1 : len0;
            if (it < lenq) {
                float* gaq = q ? ga1 : ga0;
                float iv = gaq[j], fv = gaq[128 + j], gv = gaq[256 + j], ov = gaq[384 + j];
                c = fmaf(fv, c, iv * gv);
                float hn = ov * tanh_fast(c);
                (q ? hs1 : hs0)[j] = hn;
                float* Oq = q ? Ob1 : Ob0;
                int sq = q ? s1 : s0;
                Oq[(size_t)sq * 256 + j] = hn;
            }
        }
        __syncthreads();
        if (it1 < len0) s0 += stp;
        if (it1 < len1) s1 += stp;
        xg0 = xg0n; xg1 = xg1n;
    }
    if (t < 256) {
        int q = t >> 7, j = t & 127;
        int wf = q ? wf1 : wf0;
        if (wf) {
            int bq = q ? b1 : b0;
            g_Hf[dir][bq][j] = (q ? hs1 : hs0)[j];
            g_Cf[dir][bq][j] = c;
        }
    }
}

__global__ __launch_bounds__(512, 1) void k_lstm1(
    const int* __restrict__ lengths,
    const float* __restrict__ Whh_f, const float* __restrict__ Whh_b)
{
    extern __shared__ float sm[];
    float* ws  = sm;
    float* hs0 = sm + 512 * 68;
    float* hs1 = hs0 + 128;
    float* ga0 = hs1 + 128;
    float* ga1 = ga0 + 512;
    int t   = threadIdx.x;
    int blk = blockIdx.x;
    int dir = blk >> 7;
    int p   = blk & 127;
    int bs0 = 2 * p, bs1 = 2 * p + 1;
    int len0 = lengths[bs0], len1 = lengths[bs1];
    int off0 = g_segoff[bs0], off1 = g_segoff[bs1];
    if (t < 128) { hs0[t] = 0.f; hs1[t] = 0.f; }
    const float* Gb0 = g_G1 + (size_t)off0 * 1024 + dir * 512 + t;
    const float* Gb1 = g_G1 + (size_t)off1 * 1024 + dir * 512 + t;
    float* Ob0 = g_P2 + (size_t)off0 * 256 + dir * 128;
    float* Ob1 = g_P2 + (size_t)off1 * 256 + dir * 128;
    lstm_pair_run(dir ? Whh_b : Whh_f, Gb0, Gb1, Ob0, Ob1, len0, len1, dir, t,
                  ws, hs0, hs1, ga0, ga1, 0.f,
                  (bs0 & 7) == 7, (bs1 & 7) == 7, bs0 >> 3, bs1 >> 3);
}

__global__ __launch_bounds__(512, 1) void k_lstm2(
    const int* __restrict__ lengths,
    const float* __restrict__ Whh_f, const float* __restrict__ Whh_b)
{
    extern __shared__ float sm[];
    float* ws  = sm;
    float* hs0 = sm + 512 * 68;
    float* hs1 = hs0 + 128;
    float* ga0 = hs1 + 128;
    float* ga1 = ga0 + 512;
    int t   = threadIdx.x;
    int blk = blockIdx.x;
    int dir = blk >> 4;
    int b0  = blk & 15, b1 = (blk & 15) + 16;
    int base0 = g_segoff[b0 * 8], len0 = g_segoff[b0 * 8 + 8] - base0;
    int base1 = g_segoff[b1 * 8], len1 = g_segoff[b1 * 8 + 8] - base1;
    float cini = 0.f;
    if (t < 256) {
        int q = t >> 7, j = t & 127;
        int bq = q ? b1 : b0;
        cini = g_Cf[dir][bq][j];
        (q ? hs1 : hs0)[j] = g_Hf[dir][bq][j];
    }
    const float* Gb0 = g_G2 + (size_t)base0 * 1024 + dir * 512 + t;
    const float* Gb1 = g_G2 + (size_t)base1 * 1024 + dir * 512 + t;
    float* Ob0 = g_OUT2 + (size_t)base0 * 256 + dir * 128;
    float* Ob1 = g_OUT2 + (size_t)base1 * 256 + dir * 128;
    lstm_pair_run(dir ? Whh_b : Whh_f, Gb0, Gb1, Ob0, Ob1, len0, len1, dir, t,
                  ws, hs0, hs1, ga0, ga1, cini, 0, 0, b0, b1);
}

// ---------------- emission: warp per packed row ----------------
__global__ void k_emission(const float* __restrict__ Wlin, const float* __restrict__ blin)
{
    int total = g_segoff[256];
    int gw   = (blockIdx.x * blockDim.x + threadIdx.x) >> 5;
    int nw   = (gridDim.x * blockDim.x) >> 5;
    int lane = threadIdx.x & 31;
    int k = lane & 15, half = lane >> 4;
    const float4* wr = (const float4*)(Wlin + k * 256 + half * 128);
    float4 wreg[32];
#pragma unroll
    for (int q = 0; q < 32; q++) wreg[q] = wr[q];
    float bk = blin[k];
    for (int r = gw; r < total; r += nw) {
        const float4* xr = (const float4*)(g_OUT2 + (size_t)r * 256 + half * 128);
        float a = 0.f;
#pragma unroll
        for (int q = 0; q < 32; q++) {
            float4 x = xr[q], wv = wreg[q];
            a = fmaf(x.x, wv.x, a); a = fmaf(x.y, wv.y, a);
            a = fmaf(x.z, wv.z, a); a = fmaf(x.w, wv.w, a);
        }
        a += __shfl_xor_sync(0xFFFFFFFFu, a, 16);
        if (lane < 16) g_EM[(size_t)r * 16 + k] = a + bk;
    }
}

// ---------------- Viterbi: warp per batch, K=16 in lanes ----------------
__global__ __launch_bounds__(1024, 1) void k_viterbi(
    const float* __restrict__ startv, const float* __restrict__ trans,
    const float* __restrict__ endv, float* __restrict__ out)
{
    int tid  = threadIdx.x;
    int b    = tid >> 5;
    int lane = tid & 31;
    int j    = lane & 15;
    int base = g_segoff[b * 8];
    int L    = g_segoff[b * 8 + 8] - base;
    float trC[16];
#pragma unroll
    for (int i = 0; i < 16; i++) trC[i] = trans[i * 16 + j];
    const float* em = g_EM + (size_t)base * 16;

    float sc  = startv[j] + em[j];
    float emj = em[16 + j];
    unsigned char* hist = (unsigned char*)g_HIST4;
    for (int t = 1; t < L; t++) {
        float em_next = (t + 1 < L) ? em[(t + 1) * 16 + j] : 0.0f;
        float best = -3.4e38f; int bi = 0;
#pragma unroll
        for (int i = 0; i < 16; i++) {
            float v = (__shfl_sync(0xFFFFFFFFu, sc, i) + trC[i]) + emj;
            if (v > best) { best = v; bi = i; }
        }
        sc = best;
        if (lane < 16)
            hist[((size_t)(t - 1) * 32 + b) * 16 + j] = (unsigned char)bi;
        emj = em_next;
    }
    float fin = sc + endv[j];
    float bestv = -3.4e38f; int last = 0;
#pragma unroll
    for (int i = 0; i < 16; i++) {
        float v = __shfl_sync(0xFFFFFFFFu, fin, i);
        if (v > bestv) { bestv = v; last = i; }
    }
    if (lane == 0) {
        out[32768 + b] = bestv;
        int cur = last;
        out[(TTOT - 1) * 32 + b] = (float)cur;
#pragma unroll 4
        for (int t = TTOT - 1; t >= 1; t--) {
            uint4 hrow = g_HIST4[(size_t)(t - 1) * 32 + b];
            if (t < L) {
                unsigned wv = ((const unsigned*)&hrow)[cur >> 2];
                cur = (int)((wv >> ((cur & 3) * 8)) & 0xFFu);
            }
            out[(t - 1) * 32 + b] = (float)cur;
        }
    }
}

// ---------------- launch ----------------
extern "C" void kernel_launch(void* const* d_in, const int* in_sizes, int n_in,
                              void* d_out, int out_size)
{
    const int*   texts   = (const int*)  d_in[0];
    const int*   lengths = (const int*)  d_in[1];
    const float* emb     = (const float*)d_in[2];
    const float* Wih_f   = (const float*)d_in[3];
    const float* Whh_f   = (const float*)d_in[4];
    const float* bih_f   = (const float*)d_in[5];
    const float* bhh_f   = (const float*)d_in[6];
    const float* Wih_b   = (const float*)d_in[7];
    const float* Whh_b   = (const float*)d_in[8];
    const float* bih_b   = (const float*)d_in[9];
    const float* bhh_b   = (const float*)d_in[10];
    const float* Wlin    = (const float*)d_in[11];
    const float* blin    = (const float*)d_in[12];
    const float* crf_s   = (const float*)d_in[13];
    const float* crf_t   = (const float*)d_in[14];
    const float* crf_e   = (const float*)d_in[15];
    float* out = (float*)d_out;

    cudaFuncSetAttribute(k_lstm1, cudaFuncAttributeMaxDynamicSharedMemorySize, SMEM_LSTMP);
    cudaFuncSetAttribute(k_lstm2, cudaFuncAttributeMaxDynamicSharedMemorySize, SMEM_LSTMP);
    cudaFuncSetAttribute(k_gemm3<1>, cudaFuncAttributeMaxDynamicSharedMemorySize, SMEM_G3);
    cudaFuncSetAttribute(k_gemm3<0>, cudaFuncAttributeMaxDynamicSharedMemorySize, SMEM_G3);

    float *pG1, *pP2, *pG2;
    cudaGetSymbolAddress((void**)&pG1, g_G1);
    cudaGetSymbolAddress((void**)&pP2, g_P2);
    cudaGetSymbolAddress((void**)&pG2, g_G2);

    k_offsets<<<1, 32>>>(lengths);
    k_rowmap<<<256, 128>>>(texts, lengths);
    k_convW<<<256, 256>>>(Wih_f, Wih_b, bih_f, bhh_f, bih_b, bhh_b);
    k_gemm3<1><<<dim3(256, 8), 256, SMEM_G3>>>(emb, pG1);
    k_lstm1<<<256, 512, SMEM_LSTMP>>>(lengths, Whh_f, Whh_b);
    k_gemm3<0><<<dim3(256, 8), 256, SMEM_G3>>>(pP2, pG2);
    k_lstm2<<<32, 512, SMEM_LSTMP>>>(lengths, Whh_f, Whh_b);
    k_emission<<<148, 256>>>(Wlin, blin);
    k_viterbi<<<1, 1024>>>(crf_s, crf_t, crf_e, out);
}

// round 7
// speedup vs baseline: 1.4776x; 1.4776x over previous
#include <cuda_runtime.h>
#include <mma.h>
#include <math.h>
using namespace nvcuda;

#define BATCH 32
#define NSEGC 8
#define SLEN  128
#define TTOT  1024
#define KTAG  16
#define MROWS 32768

// ---------------- device scratch ----------------
__device__ float g_G1 [(size_t)MROWS * 1024];   // stage1 x-gates (packed rows)
__device__ float g_P2 [(size_t)MROWS * 256];    // packed lstm2 input (= packed stage1 out)
__device__ float g_G2 [(size_t)MROWS * 1024];   // stage2 x-gates (packed rows)
__device__ float g_OUT2[(size_t)MROWS * 256];   // stage2 outputs (packed)
__device__ float g_EM [(size_t)MROWS * KTAG];   // emissions (packed)
__device__ float g_Whi[1024 * 256];             // tf32-hi of [Wf;Wb]
__device__ float g_Wlo[1024 * 256];             // tf32-lo of [Wf;Wb]
__device__ float g_bias[1024];                  // bih+bhh, f then b
__device__ int   g_segoff[257];
__device__ int   g_tokmap[MROWS];
__device__ float g_Hf[2][BATCH][128];
__device__ float g_Cf[2][BATCH][128];

// ---------------- helpers ----------------
__device__ __forceinline__ float f2tf(float x)
{
    float r;
    asm("cvt.rna.tf32.f32 %0, %1;" : "=f"(r) : "f"(x));
    return r;
}
__device__ __forceinline__ float sig_fast(float x)
{
    return __fdividef(1.0f, 1.0f + __expf(-x));
}
__device__ __forceinline__ float tanh_fast(float x)
{
    return 1.0f - 2.0f * __fdividef(1.0f, 1.0f + __expf(2.0f * x));
}

// ---------------- offsets: warp scan of 256 lengths ----------------
__global__ void k_offsets(const int* __restrict__ lengths)
{
    int lane = threadIdx.x;
    int v[8], s = 0;
#pragma unroll
    for (int i = 0; i < 8; i++) { v[i] = lengths[lane * 8 + i]; s += v[i]; }
    int inc = s;
#pragma unroll
    for (int d = 1; d < 32; d <<= 1) {
        int o = __shfl_up_sync(0xFFFFFFFFu, inc, d);
        if (lane >= d) inc += o;
    }
    int run = inc - s;                    // exclusive prefix of lane sums
#pragma unroll
    for (int i = 0; i < 8; i++) { g_segoff[lane * 8 + i] = run; run += v[i]; }
    if (lane == 31) g_segoff[256] = run;
}

__global__ void k_rowmap(const int* __restrict__ texts, const int* __restrict__ lengths)
{
    int bs = blockIdx.x;
    int len = lengths[bs];
    int off = g_segoff[bs];
    int s = threadIdx.x;
    if (s < len) g_tokmap[off + s] = texts[bs * 128 + s];
}

// ---------------- weight preconversion: [Wf;Wb] -> tf32 hi/lo, bias sum ----------------
__global__ void k_convW(const float* __restrict__ Wf, const float* __restrict__ Wb,
                        const float* __restrict__ b1f, const float* __restrict__ b2f,
                        const float* __restrict__ b1b, const float* __restrict__ b2b)
{
    int idx = blockIdx.x * 256 + threadIdx.x;
#pragma unroll
    for (int e = 0; e < 4; e++) {
        int i = idx * 4 + e;
        int n = i >> 8, k = i & 255;
        float v = (n < 512) ? Wf[n * 256 + k] : Wb[(n - 512) * 256 + k];
        float hi = f2tf(v);
        g_Whi[i] = hi;
        g_Wlo[i] = f2tf(v - hi);
    }
    if (idx < 1024) {
        g_bias[idx] = (idx < 512) ? (b1f[idx] + b2f[idx])
                                  : (b1b[idx - 512] + b2b[idx - 512]);
    }
}

// ---------------- 3xTF32 tensor-core GEMM, preconverted weights ----------------
#define SMEM_G3 ((4 * 128 * 40 + 16 * 136) * 4)

template<int GATHER>
__global__ __launch_bounds__(256, 2) void k_gemm3(
    const float* __restrict__ A, float* __restrict__ C)
{
    int total = g_segoff[256];
    int bm = blockIdx.x * 128;
    if (bm >= total) return;
    int bn = blockIdx.y * 128;

    extern __shared__ float sm[];
    float* Ash = sm;                       // [128][40]
    float* Asl = sm + 128 * 40;
    float* Bsh = sm + 2 * 128 * 40;
    float* Bsl = sm + 3 * 128 * 40;
    float* bias_s = sm + 4 * 128 * 40;     // [16][136]

    int tid = threadIdx.x;
    for (int i = tid; i < 16 * 128; i += 256) {
        int r = i >> 7, c = i & 127;
        bias_s[r * 136 + c] = g_bias[bn + c];
    }

    int r0 = tid >> 3;
    int f4 = (tid & 7) * 4;
    const float* arow[4];
#pragma unroll
    for (int p = 0; p < 4; p++) {
        int pr = bm + r0 + 32 * p;
        if (GATHER) {
            int tok = (pr < total) ? g_tokmap[pr] : 0;
            arow[p] = A + (size_t)tok * 256;
        } else {
            arow[p] = A + (size_t)pr * 256;
        }
    }
    const float* whrow = g_Whi + (size_t)(bn + r0) * 256;
    const float* wlrow = g_Wlo + (size_t)(bn + r0) * 256;

    int wid = tid >> 5;
    int lm = (wid & 3) * 32;
    int ln = (wid >> 2) * 64;

    wmma::fragment<wmma::accumulator, 16, 16, 8, float> acc[2][4];
    __syncthreads();
#pragma unroll
    for (int mi = 0; mi < 2; mi++)
#pragma unroll
        for (int ni = 0; ni < 4; ni++)
            wmma::load_matrix_sync(acc[mi][ni], bias_s + ln + ni * 16, 136,
                                   wmma::mem_row_major);

    for (int k0 = 0; k0 < 256; k0 += 32) {
        float4 av[4], bh4[4], bl4[4];
#pragma unroll
        for (int p = 0; p < 4; p++) {
            av[p]  = *(const float4*)(arow[p] + k0 + f4);
            bh4[p] = *(const float4*)(whrow + (size_t)p * 32 * 256 + k0 + f4);
            bl4[p] = *(const float4*)(wlrow + (size_t)p * 32 * 256 + k0 + f4);
        }
        __syncthreads();
#pragma unroll
        for (int p = 0; p < 4; p++) {
            int row = (r0 + 32 * p) * 40 + f4;
            float h0 = f2tf(av[p].x), h1 = f2tf(av[p].y),
                  h2 = f2tf(av[p].z), h3 = f2tf(av[p].w);
            *(float4*)&Ash[row] = make_float4(h0, h1, h2, h3);
            *(float4*)&Asl[row] = make_float4(f2tf(av[p].x - h0), f2tf(av[p].y - h1),
                                              f2tf(av[p].z - h2), f2tf(av[p].w - h3));
            *(float4*)&Bsh[row] = bh4[p];
            *(float4*)&Bsl[row] = bl4[p];
        }
        __syncthreads();
#pragma unroll
        for (int ks = 0; ks < 4; ks++) {
            wmma::fragment<wmma::matrix_a, 16, 16, 8, wmma::precision::tf32,
                           wmma::row_major> ah[2], al[2];
#pragma unroll
            for (int mi = 0; mi < 2; mi++) {
                wmma::load_matrix_sync(ah[mi], Ash + (lm + mi * 16) * 40 + ks * 8, 40);
                wmma::load_matrix_sync(al[mi], Asl + (lm + mi * 16) * 40 + ks * 8, 40);
            }
#pragma unroll
            for (int ni = 0; ni < 4; ni++) {
                wmma::fragment<wmma::matrix_b, 16, 16, 8, wmma::precision::tf32,
                               wmma::col_major> bh, bl;
                wmma::load_matrix_sync(bh, Bsh + (ln + ni * 16) * 40 + ks * 8, 40);
                wmma::load_matrix_sync(bl, Bsl + (ln + ni * 16) * 40 + ks * 8, 40);
#pragma unroll
                for (int mi = 0; mi < 2; mi++) {
                    wmma::mma_sync(acc[mi][ni], ah[mi], bl, acc[mi][ni]);
                    wmma::mma_sync(acc[mi][ni], al[mi], bh, acc[mi][ni]);
                    wmma::mma_sync(acc[mi][ni], ah[mi], bh, acc[mi][ni]);
                }
            }
        }
    }
#pragma unroll
    for (int mi = 0; mi < 2; mi++)
#pragma unroll
        for (int ni = 0; ni < 4; ni++)
            wmma::store_matrix_sync(
                C + (size_t)(bm + lm + mi * 16) * 1024 + bn + ln + ni * 16,
                acc[mi][ni], 1024, wmma::mem_row_major);
}

// ---------------- LSTM recurrent core (unpaired, fast activations) ----------------
#define SMEM_LSTM ((512 * 68 + 128 + 512) * 4)

__device__ __forceinline__ void lstm_run(
    const float* __restrict__ Whh, const float* __restrict__ Gbase,
    float* __restrict__ Obase, int len, int dir, int t,
    float* ws, float* hs, float* ga,
    float h_init, float c_init, int write_final, int b)
{
    const float* wr = Whh + t * 128;
    float w[64];
#pragma unroll
    for (int q = 0; q < 16; q++) {
        float4 v = *(const float4*)(wr + q * 4);
        w[4*q]=v.x; w[4*q+1]=v.y; w[4*q+2]=v.z; w[4*q+3]=v.w;
    }
    float* wsr = ws + t * 68;
#pragma unroll
    for (int q = 0; q < 16; q++)
        *(float4*)(wsr + 4 * q) = *(const float4*)(wr + 64 + 4 * q);

    float c = c_init;
    if (t < 128) hs[t] = h_init;
    __syncthreads();

    int s    = dir ? (len - 1) : 0;
    int step = dir ? -1 : 1;
    bool isg = ((t >> 7) == 2);
    float xg = Gbase[(size_t)s * 1024];
    for (int it = 0; it < len; it++) {
        int s_next = s + step;
        float xg_next = (it + 1 < len) ? Gbase[(size_t)s_next * 1024] : 0.0f;
        float acca = xg, accb = 0.f;
        const float4* h4 = (const float4*)hs;
#pragma unroll
        for (int q = 0; q < 16; q++) {
            float4 hv = h4[q];
            acca = fmaf(w[4*q  ], hv.x, acca);
            accb = fmaf(w[4*q+1], hv.y, accb);
            acca = fmaf(w[4*q+2], hv.z, acca);
            accb = fmaf(w[4*q+3], hv.w, accb);
        }
#pragma unroll
        for (int q = 0; q < 16; q++) {
            float4 wv = *(const float4*)(wsr + 4 * q);
            float4 hv = h4[16 + q];
            acca = fmaf(wv.x, hv.x, acca);
            accb = fmaf(wv.y, hv.y, accb);
            acca = fmaf(wv.z, hv.z, acca);
            accb = fmaf(wv.w, hv.w, accb);
        }
        float acc = acca + accb;
        ga[t] = isg ? tanh_fast(acc) : sig_fast(acc);
        __syncthreads();
        if (t < 128) {
            float iv = ga[t], fv = ga[128 + t], gv = ga[256 + t], ov = ga[384 + t];
            c = fmaf(fv, c, iv * gv);
            float hn = ov * tanh_fast(c);
            hs[t] = hn;
            Obase[(size_t)s * 256 + t] = hn;
        }
        __syncthreads();
        xg = xg_next;
        s  = s_next;
    }
    if (write_final && t < 128) {
        g_Hf[dir][b][t] = hs[t];
        g_Cf[dir][b][t] = c;
    }
}

__global__ __launch_bounds__(512, 1) void k_lstm1(
    const int* __restrict__ lengths,
    const float* __restrict__ Whh_f, const float* __restrict__ Whh_b)
{
    extern __shared__ float sm[];
    float* ws = sm;
    float* hs = sm + 512 * 68;
    float* ga = hs + 128;
    int t   = threadIdx.x;
    int blk = blockIdx.x;
    int dir = blk >> 8;
    int b   = (blk & 255) >> 3;
    int seg = blk & 7;
    int bs  = b * NSEGC + seg;
    int len = lengths[bs];
    int off = g_segoff[bs];
    const float* Gbase = g_G1 + (size_t)off * 1024 + dir * 512 + t;
    float* Obase = g_P2 + (size_t)off * 256 + dir * 128;
    lstm_run(dir ? Whh_b : Whh_f, Gbase, Obase, len, dir, t, ws, hs, ga,
             0.0f, 0.0f, (seg == NSEGC - 1), b);
}

__global__ __launch_bounds__(512, 1) void k_lstm2(
    const int* __restrict__ lengths,
    const float* __restrict__ Whh_f, const float* __restrict__ Whh_b)
{
    extern __shared__ float sm[];
    float* ws = sm;
    float* hs = sm + 512 * 68;
    float* ga = hs + 128;
    int t   = threadIdx.x;
    int blk = blockIdx.x;
    int dir = blk >> 5;
    int b   = blk & 31;
    int base = g_segoff[b * 8];
    int len  = g_segoff[b * 8 + 8] - base;
    float hi = (t < 128) ? g_Hf[dir][b][t & 127] : 0.0f;
    float ci = (t < 128) ? g_Cf[dir][b][t & 127] : 0.0f;
    const float* Gbase = g_G2 + (size_t)base * 1024 + dir * 512 + t;
    float* Obase = g_OUT2 + (size_t)base * 256 + dir * 128;
    lstm_run(dir ? Whh_b : Whh_f, Gbase, Obase, len, dir, t, ws, hs, ga,
             hi, ci, 0, b);
}

// ---------------- emission: warp per packed row ----------------
__global__ void k_emission(const float* __restrict__ Wlin, const float* __restrict__ blin)
{
    int total = g_segoff[256];
    int gw   = (blockIdx.x * blockDim.x + threadIdx.x) >> 5;
    int nw   = (gridDim.x * blockDim.x) >> 5;
    int lane = threadIdx.x & 31;
    int k = lane & 15, half = lane >> 4;
    const float4* wr = (const float4*)(Wlin + k * 256 + half * 128);
    float4 wreg[32];
#pragma unroll
    for (int q = 0; q < 32; q++) wreg[q] = wr[q];
    float bk = blin[k];
    for (int r = gw; r < total; r += nw) {
        const float4* xr = (const float4*)(g_OUT2 + (size_t)r * 256 + half * 128);
        float a = 0.f;
#pragma unroll
        for (int q = 0; q < 32; q++) {
            float4 x = xr[q], wv = wreg[q];
            a = fmaf(x.x, wv.x, a); a = fmaf(x.y, wv.y, a);
            a = fmaf(x.z, wv.z, a); a = fmaf(x.w, wv.w, a);
        }
        a += __shfl_xor_sync(0xFFFFFFFFu, a, 16);
        if (lane < 16) g_EM[(size_t)r * 16 + k] = a + bk;
    }
}

// ---------------- Viterbi: one block per batch, smem history ----------------
__global__ __launch_bounds__(32, 1) void k_viterbi(
    const float* __restrict__ startv, const float* __restrict__ trans,
    const float* __restrict__ endv, float* __restrict__ out)
{
    __shared__ unsigned char hist[(TTOT - 1) * 16];
    int b    = blockIdx.x;
    int lane = threadIdx.x;
    int j    = lane & 15;
    int base = g_segoff[b * 8];
    int L    = g_segoff[b * 8 + 8] - base;
    float trC[16];
#pragma unroll
    for (int i = 0; i < 16; i++) trC[i] = trans[i * 16 + j];
    const float* em = g_EM + (size_t)base * 16;

    float sc  = startv[j] + em[j];
    float emj = em[16 + j];
    for (int t = 1; t < L; t++) {
        float em_next = (t + 1 < L) ? em[(t + 1) * 16 + j] : 0.0f;
        float best = -3.4e38f; int bi = 0;
#pragma unroll
        for (int i = 0; i < 16; i++) {
            float v = (__shfl_sync(0xFFFFFFFFu, sc, i) + trC[i]) + emj;
            if (v > best) { best = v; bi = i; }
        }
        sc = best;
        if (lane < 16) hist[(t - 1) * 16 + j] = (unsigned char)bi;
        emj = em_next;
    }
    float fin = sc + endv[j];
    float bestv = -3.4e38f; int last = 0;
#pragma unroll
    for (int i = 0; i < 16; i++) {
        float v = __shfl_sync(0xFFFFFFFFu, fin, i);
        if (v > bestv) { bestv = v; last = i; }
    }
    __syncwarp();
    if (lane == 0) {
        out[32768 + b] = bestv;
        int cur = last;
        out[(TTOT - 1) * 32 + b] = (float)cur;
        // positions >= L-1 all carry 'last'
        for (int t = TTOT - 1; t >= L; t--) out[(t - 1) * 32 + b] = (float)cur;
        for (int t = L - 1; t >= 1; t--) {
            cur = hist[(t - 1) * 16 + cur];
            out[(t - 1) * 32 + b] = (float)cur;
        }
    }
}

// ---------------- launch ----------------
extern "C" void kernel_launch(void* const* d_in, const int* in_sizes, int n_in,
                              void* d_out, int out_size)
{
    const int*   texts   = (const int*)  d_in[0];
    const int*   lengths = (const int*)  d_in[1];
    const float* emb     = (const float*)d_in[2];
    const float* Wih_f   = (const float*)d_in[3];
    const float* Whh_f   = (const float*)d_in[4];
    const float* bih_f   = (const float*)d_in[5];
    const float* bhh_f   = (const float*)d_in[6];
    const float* Wih_b   = (const float*)d_in[7];
    const float* Whh_b   = (const float*)d_in[8];
    const float* bih_b   = (const float*)d_in[9];
    const float* bhh_b   = (const float*)d_in[10];
    const float* Wlin    = (const float*)d_in[11];
    const float* blin    = (const float*)d_in[12];
    const float* crf_s   = (const float*)d_in[13];
    const float* crf_t   = (const float*)d_in[14];
    const float* crf_e   = (const float*)d_in[15];
    float* out = (float*)d_out;

    cudaFuncSetAttribute(k_lstm1, cudaFuncAttributeMaxDynamicSharedMemorySize, SMEM_LSTM);
    cudaFuncSetAttribute(k_lstm2, cudaFuncAttributeMaxDynamicSharedMemorySize, SMEM_LSTM);
    cudaFuncSetAttribute(k_gemm3<1>, cudaFuncAttributeMaxDynamicSharedMemorySize, SMEM_G3);
    cudaFuncSetAttribute(k_gemm3<0>, cudaFuncAttributeMaxDynamicSharedMemorySize, SMEM_G3);

    float *pG1, *pP2, *pG2;
    cudaGetSymbolAddress((void**)&pG1, g_G1);
    cudaGetSymbolAddress((void**)&pP2, g_P2);
    cudaGetSymbolAddress((void**)&pG2, g_G2);

    k_offsets<<<1, 32>>>(lengths);
    k_rowmap<<<256, 128>>>(texts, lengths);
    k_convW<<<256, 256>>>(Wih_f, Wih_b, bih_f, bhh_f, bih_b, bhh_b);
    k_gemm3<1><<<dim3(256, 8), 256, SMEM_G3>>>(emb, pG1);
    k_lstm1<<<512, 512, SMEM_LSTM>>>(lengths, Whh_f, Whh_b);
    k_gemm3<0><<<dim3(256, 8), 256, SMEM_G3>>>(pP2, pG2);
    k_lstm2<<<64, 512, SMEM_LSTM>>>(lengths, Whh_f, Whh_b);
    k_emission<<<148, 256>>>(Wlin, blin);
    k_viterbi<<<32, 32>>>(crf_s, crf_t, crf_e, out);
}

// round 9
// speedup vs baseline: 1.5091x; 1.0214x over previous
#include <cuda_runtime.h>
#include <cstdint>
#include <mma.h>
#include <math.h>
using namespace nvcuda;

#define BATCH 32
#define NSEGC 8
#define SLEN  128
#define TTOT  1024
#define KTAG  16
#define MROWS 32768

// ---------------- device scratch ----------------
__device__ float g_G1 [(size_t)MROWS * 1024];   // stage1 x-gates (packed rows)
__device__ float g_P2 [(size_t)MROWS * 256];    // packed lstm2 input (= packed stage1 out)
__device__ float g_G2 [(size_t)MROWS * 1024];   // stage2 x-gates (packed rows)
__device__ float g_OUT2[(size_t)MROWS * 256];   // stage2 outputs (packed)
__device__ float g_EM [(size_t)MROWS * KTAG];   // emissions (packed)
__device__ float g_Whi[1024 * 256];             // tf32-hi of [Wf;Wb]
__device__ float g_Wlo[1024 * 256];             // tf32-lo of [Wf;Wb]
__device__ float g_bias[1024];                  // bih+bhh, f then b
__device__ int   g_segoff[257];
__device__ int   g_tokmap[MROWS];
__device__ float g_Hf[2][BATCH][128];
__device__ float g_Cf[2][BATCH][128];

// ---------------- helpers ----------------
__device__ __forceinline__ float f2tf(float x)
{
    float r;
    asm("cvt.rna.tf32.f32 %0, %1;" : "=f"(r) : "f"(x));
    return r;
}
__device__ __forceinline__ float sig_fast(float x)
{
    return __fdividef(1.0f, 1.0f + __expf(-x));
}
__device__ __forceinline__ float tanh_fast(float x)
{
    return 1.0f - 2.0f * __fdividef(1.0f, 1.0f + __expf(2.0f * x));
}
__device__ __forceinline__ unsigned smem_u32(const void* p)
{
    return (unsigned)__cvta_generic_to_shared(p);
}
__device__ __forceinline__ unsigned mapa_u32(unsigned a, unsigned r)
{
    unsigned d;
    asm("mapa.shared::cluster.u32 %0, %1, %2;" : "=r"(d) : "r"(a), "r"(r));
    return d;
}
__device__ __forceinline__ void mbar_init(unsigned a, unsigned cnt)
{
    asm volatile("mbarrier.init.shared.b64 [%0], %1;" :: "r"(a), "r"(cnt) : "memory");
}
__device__ __forceinline__ void mbar_arrive_local(unsigned a)
{
    asm volatile("mbarrier.arrive.shared::cta.b64 _, [%0];" :: "r"(a) : "memory");
}
__device__ __forceinline__ void mbar_arrive_remote(unsigned a)
{
    asm volatile("mbarrier.arrive.release.cluster.shared::cluster.b64 _, [%0];"
                 :: "r"(a) : "memory");
}
__device__ __forceinline__ void mbar_wait_cluster(unsigned a, unsigned phase)
{
    asm volatile(
        "{\n\t"
        ".reg .pred P;\n\t"
        "WLOOP%=:\n\t"
        "mbarrier.try_wait.parity.acquire.cluster.shared::cta.b64 P, [%0], %1;\n\t"
        "@!P bra WLOOP%=;\n\t"
        "}"
        :: "r"(a), "r"(phase) : "memory");
}
__device__ __forceinline__ void st_shared_cluster_f32(unsigned a, float v)
{
    asm volatile("st.shared::cluster.f32 [%0], %1;" :: "r"(a), "f"(v) : "memory");
}
__device__ __forceinline__ void cluster_sync_()
{
    asm volatile("barrier.cluster.arrive.aligned;" ::: "memory");
    asm volatile("barrier.cluster.wait.aligned;" ::: "memory");
}

// ---------------- offsets: warp scan of 256 lengths ----------------
__global__ void k_offsets(const int* __restrict__ lengths)
{
    int lane = threadIdx.x;
    int v[8], s = 0;
#pragma unroll
    for (int i = 0; i < 8; i++) { v[i] = lengths[lane * 8 + i]; s += v[i]; }
    int inc = s;
#pragma unroll
    for (int d = 1; d < 32; d <<= 1) {
        int o = __shfl_up_sync(0xFFFFFFFFu, inc, d);
        if (lane >= d) inc += o;
    }
    int run = inc - s;                    // exclusive prefix of lane sums
#pragma unroll
    for (int i = 0; i < 8; i++) { g_segoff[lane * 8 + i] = run; run += v[i]; }
    if (lane == 31) g_segoff[256] = run;
}

__global__ void k_rowmap(const int* __restrict__ texts, const int* __restrict__ lengths)
{
    int bs = blockIdx.x;
    int len = lengths[bs];
    int off = g_segoff[bs];
    int s = threadIdx.x;
    if (s < len) g_tokmap[off + s] = texts[bs * 128 + s];
}

// ---------------- weight preconversion: [Wf;Wb] -> tf32 hi/lo, bias sum ----------------
__global__ void k_convW(const float* __restrict__ Wf, const float* __restrict__ Wb,
                        const float* __restrict__ b1f, const float* __restrict__ b2f,
                        const float* __restrict__ b1b, const float* __restrict__ b2b)
{
    int idx = blockIdx.x * 256 + threadIdx.x;
#pragma unroll
    for (int e = 0; e < 4; e++) {
        int i = idx * 4 + e;
        int n = i >> 8, k = i & 255;
        float v = (n < 512) ? Wf[n * 256 + k] : Wb[(n - 512) * 256 + k];
        float hi = f2tf(v);
        g_Whi[i] = hi;
        g_Wlo[i] = f2tf(v - hi);
    }
    if (idx < 1024) {
        g_bias[idx] = (idx < 512) ? (b1f[idx] + b2f[idx])
                                  : (b1b[idx - 512] + b2b[idx - 512]);
    }
}

// ---------------- 3xTF32 tensor-core GEMM, preconverted weights ----------------
#define SMEM_G3 ((4 * 128 * 40 + 16 * 136) * 4)

template<int GATHER>
__global__ __launch_bounds__(256, 2) void k_gemm3(
    const float* __restrict__ A, float* __restrict__ C)
{
    int total = g_segoff[256];
    int bm = blockIdx.x * 128;
    if (bm >= total) return;
    int bn = blockIdx.y * 128;

    extern __shared__ float sm[];
    float* Ash = sm;                       // [128][40]
    float* Asl = sm + 128 * 40;
    float* Bsh = sm + 2 * 128 * 40;
    float* Bsl = sm + 3 * 128 * 40;
    float* bias_s = sm + 4 * 128 * 40;     // [16][136]

    int tid = threadIdx.x;
    for (int i = tid; i < 16 * 128; i += 256) {
        int r = i >> 7, c = i & 127;
        bias_s[r * 136 + c] = g_bias[bn + c];
    }

    int r0 = tid >> 3;
    int f4 = (tid & 7) * 4;
    const float* arow[4];
#pragma unroll
    for (int p = 0; p < 4; p++) {
        int pr = bm + r0 + 32 * p;
        if (GATHER) {
            int tok = (pr < total) ? g_tokmap[pr] : 0;
            arow[p] = A + (size_t)tok * 256;
        } else {
            arow[p] = A + (size_t)pr * 256;
        }
    }
    const float* whrow = g_Whi + (size_t)(bn + r0) * 256;
    const float* wlrow = g_Wlo + (size_t)(bn + r0) * 256;

    int wid = tid >> 5;
    int lm = (wid & 3) * 32;
    int ln = (wid >> 2) * 64;

    wmma::fragment<wmma::accumulator, 16, 16, 8, float> acc[2][4];
    __syncthreads();
#pragma unroll
    for (int mi = 0; mi < 2; mi++)
#pragma unroll
        for (int ni = 0; ni < 4; ni++)
            wmma::load_matrix_sync(acc[mi][ni], bias_s + ln + ni * 16, 136,
                                   wmma::mem_row_major);

    for (int k0 = 0; k0 < 256; k0 += 32) {
        float4 av[4], bh4[4], bl4[4];
#pragma unroll
        for (int p = 0; p < 4; p++) {
            av[p]  = *(const float4*)(arow[p] + k0 + f4);
            bh4[p] = *(const float4*)(whrow + (size_t)p * 32 * 256 + k0 + f4);
            bl4[p] = *(const float4*)(wlrow + (size_t)p * 32 * 256 + k0 + f4);
        }
        __syncthreads();
#pragma unroll
        for (int p = 0; p < 4; p++) {
            int row = (r0 + 32 * p) * 40 + f4;
            float h0 = f2tf(av[p].x), h1 = f2tf(av[p].y),
                  h2 = f2tf(av[p].z), h3 = f2tf(av[p].w);
            *(float4*)&Ash[row] = make_float4(h0, h1, h2, h3);
            *(float4*)&Asl[row] = make_float4(f2tf(av[p].x - h0), f2tf(av[p].y - h1),
                                              f2tf(av[p].z - h2), f2tf(av[p].w - h3));
            *(float4*)&Bsh[row] = bh4[p];
            *(float4*)&Bsl[row] = bl4[p];
        }
        __syncthreads();
#pragma unroll
        for (int ks = 0; ks < 4; ks++) {
            wmma::fragment<wmma::matrix_a, 16, 16, 8, wmma::precision::tf32,
                           wmma::row_major> ah[2], al[2];
#pragma unroll
            for (int mi = 0; mi < 2; mi++) {
                wmma::load_matrix_sync(ah[mi], Ash + (lm + mi * 16) * 40 + ks * 8, 40);
                wmma::load_matrix_sync(al[mi], Asl + (lm + mi * 16) * 40 + ks * 8, 40);
            }
#pragma unroll
            for (int ni = 0; ni < 4; ni++) {
                wmma::fragment<wmma::matrix_b, 16, 16, 8, wmma::precision::tf32,
                               wmma::col_major> bh, bl;
                wmma::load_matrix_sync(bh, Bsh + (ln + ni * 16) * 40 + ks * 8, 40);
                wmma::load_matrix_sync(bl, Bsl + (ln + ni * 16) * 40 + ks * 8, 40);
#pragma unroll
                for (int mi = 0; mi < 2; mi++) {
                    wmma::mma_sync(acc[mi][ni], ah[mi], bl, acc[mi][ni]);
                    wmma::mma_sync(acc[mi][ni], al[mi], bh, acc[mi][ni]);
                    wmma::mma_sync(acc[mi][ni], ah[mi], bh, acc[mi][ni]);
                }
            }
        }
    }
#pragma unroll
    for (int mi = 0; mi < 2; mi++)
#pragma unroll
        for (int ni = 0; ni < 4; ni++)
            wmma::store_matrix_sync(
                C + (size_t)(bm + lm + mi * 16) * 1024 + bn + ln + ni * 16,
                acc[mi][ni], 1024, wmma::mem_row_major);
}

// ---------------- LSTM1 recurrent core (unpaired, fast activations) ----------------
#define SMEM_LSTM ((512 * 68 + 128 + 512) * 4)

__device__ __forceinline__ void lstm_run(
    const float* __restrict__ Whh, const float* __restrict__ Gbase,
    float* __restrict__ Obase, int len, int dir, int t,
    float* ws, float* hs, float* ga,
    float h_init, float c_init, int write_final, int b)
{
    const float* wr = Whh + t * 128;
    float w[64];
#pragma unroll
    for (int q = 0; q < 16; q++) {
        float4 v = *(const float4*)(wr + q * 4);
        w[4*q]=v.x; w[4*q+1]=v.y; w[4*q+2]=v.z; w[4*q+3]=v.w;
    }
    float* wsr = ws + t * 68;
#pragma unroll
    for (int q = 0; q < 16; q++)
        *(float4*)(wsr + 4 * q) = *(const float4*)(wr + 64 + 4 * q);

    float c = c_init;
    if (t < 128) hs[t] = h_init;
    __syncthreads();

    int s    = dir ? (len - 1) : 0;
    int step = dir ? -1 : 1;
    bool isg = ((t >> 7) == 2);
    float xg = Gbase[(size_t)s * 1024];
    for (int it = 0; it < len; it++) {
        int s_next = s + step;
        float xg_next = (it + 1 < len) ? Gbase[(size_t)s_next * 1024] : 0.0f;
        float acca = xg, accb = 0.f;
        const float4* h4 = (const float4*)hs;
#pragma unroll
        for (int q = 0; q < 16; q++) {
            float4 hv = h4[q];
            acca = fmaf(w[4*q  ], hv.x, acca);
            accb = fmaf(w[4*q+1], hv.y, accb);
            acca = fmaf(w[4*q+2], hv.z, acca);
            accb = fmaf(w[4*q+3], hv.w, accb);
        }
#pragma unroll
        for (int q = 0; q < 16; q++) {
            float4 wv = *(const float4*)(wsr + 4 * q);
            float4 hv = h4[16 + q];
            acca = fmaf(wv.x, hv.x, acca);
            accb = fmaf(wv.y, hv.y, accb);
            acca = fmaf(wv.z, hv.z, acca);
            accb = fmaf(wv.w, hv.w, accb);
        }
        float acc = acca + accb;
        ga[t] = isg ? tanh_fast(acc) : sig_fast(acc);
        __syncthreads();
        if (t < 128) {
            float iv = ga[t], fv = ga[128 + t], gv = ga[256 + t], ov = ga[384 + t];
            c = fmaf(fv, c, iv * gv);
            float hn = ov * tanh_fast(c);
            hs[t] = hn;
            Obase[(size_t)s * 256 + t] = hn;
        }
        __syncthreads();
        xg = xg_next;
        s  = s_next;
    }
    if (write_final && t < 128) {
        g_Hf[dir][b][t] = hs[t];
        g_Cf[dir][b][t] = c;
    }
}

__global__ __launch_bounds__(512, 1) void k_lstm1(
    const int* __restrict__ lengths,
    const float* __restrict__ Whh_f, const float* __restrict__ Whh_b)
{
    extern __shared__ float sm[];
    float* ws = sm;
    float* hs = sm + 512 * 68;
    float* ga = hs + 128;
    int t   = threadIdx.x;
    int blk = blockIdx.x;
    int dir = blk >> 8;
    int b   = (blk & 255) >> 3;
    int seg = blk & 7;
    int bs  = b * NSEGC + seg;
    int len = lengths[bs];
    int off = g_segoff[bs];
    const float* Gbase = g_G1 + (size_t)off * 1024 + dir * 512 + t;
    float* Obase = g_P2 + (size_t)off * 256 + dir * 128;
    lstm_run(dir ? Whh_b : Whh_f, Gbase, Obase, len, dir, t, ws, hs, ga,
             0.0f, 0.0f, (seg == NSEGC - 1), b);
}

// ---------------- LSTM2: 2-CTA cluster per (b,dir), weights all in registers -------
// CTA rank r owns gate rows [r*256, r*256+256). Thread t: row=t>>1, half=t&1,
// 64 weights in regs. Gates exchanged cross-CTA via st.shared::cluster into the
// peer's double-buffered ga[parity][512]; one mbarrier round per step
// (512 arrivals: 256 local even lanes + 256 remote even lanes). Both CTAs run
// the identical c/h update (c replicated), so h stays CTA-local.
__global__ __launch_bounds__(512, 1) __cluster_dims__(2, 1, 1)
void k_lstm2c(const float* __restrict__ Whh_f, const float* __restrict__ Whh_b)
{
    __shared__ float ga[2][512];
    __shared__ float hs[128];
    __shared__ __align__(8) unsigned long long mbar_store;

    unsigned rank;
    asm("mov.u32 %0, %%cluster_ctarank;" : "=r"(rank));
    int t   = threadIdx.x;
    int cid = blockIdx.x >> 1;          // cluster index: dir*32 + b
    int dir = cid >> 5;
    int b   = cid & 31;

    int base = g_segoff[b * 8];
    int len  = g_segoff[b * 8 + 8] - base;

    int row  = t >> 1, half = t & 1;
    int grow = (int)rank * 256 + row;   // global gate row 0..511

    const float* Whh = dir ? Whh_b : Whh_f;
    float w[64];
    const float4* wr = (const float4*)(Whh + (size_t)grow * 128 + half * 64);
#pragma unroll
    for (int q = 0; q < 16; q++) {
        float4 v = wr[q];
        w[4*q]=v.x; w[4*q+1]=v.y; w[4*q+2]=v.z; w[4*q+3]=v.w;
    }

    unsigned bar      = smem_u32(&mbar_store);
    unsigned peer_bar = mapa_u32(bar, rank ^ 1);
    unsigned ga_u32   = smem_u32(&ga[0][0]);
    unsigned peer_ga  = mapa_u32(ga_u32 + (unsigned)grow * 4, rank ^ 1); // +p*2048 per step

    float c = 0.f;
    if (t < 128) { hs[t] = g_Hf[dir][b][t]; c = g_Cf[dir][b][t]; }
    if (t == 0) mbar_init(bar, 512);
    __syncthreads();
    cluster_sync_();                    // mbar + hs visible cluster-wide

    int stp = dir ? -1 : 1;
    int s   = dir ? (len - 1) : 0;
    const float* G = g_G2 + (size_t)base * 1024 + dir * 512 + grow;
    float xg = (half == 0) ? G[(size_t)s * 1024] : 0.f;
    bool isg = (rank == 1) && (row < 128);      // g-gate rows 256..383
    float* Orow = g_OUT2 + (size_t)base * 256 + dir * 128;

    for (int it = 0; it < len; it++) {
        int p = it & 1;
        float xgn = 0.f;
        if (half == 0 && it + 1 < len) xgn = G[(size_t)(s + stp) * 1024];

        float a0 = xg, a1 = 0.f;
        const float4* h4 = (const float4*)(hs + half * 64);
#pragma unroll
        for (int q = 0; q < 16; q++) {
            float4 hv = h4[q];
            a0 = fmaf(w[4*q  ], hv.x, a0);
            a1 = fmaf(w[4*q+1], hv.y, a1);
            a0 = fmaf(w[4*q+2], hv.z, a0);
            a1 = fmaf(w[4*q+3], hv.w, a1);
        }
        float part = a0 + a1;
        float tot  = part + __shfl_xor_sync(0xFFFFFFFFu, part, 1);
        if (half == 0) {
            float act = isg ? tanh_fast(tot) : sig_fast(tot);
            ga[p][grow] = act;
            st_shared_cluster_f32(peer_ga + (unsigned)p * 2048, act);
            mbar_arrive_local(bar);
            mbar_arrive_remote(peer_bar);
        }
        if (t < 128) {
            mbar_wait_cluster(bar, (unsigned)p);
            float iv = ga[p][t], fv = ga[p][128 + t], gv = ga[p][256 + t], ov = ga[p][384 + t];
            c = fmaf(fv, c, iv * gv);
            float hn = ov * tanh_fast(c);
            hs[t] = hn;
            if (rank == 0) Orow[(size_t)s * 256 + t] = hn;
        }
        __syncthreads();
        s += stp;
        xg = xgn;
    }
    cluster_sync_();                    // lifetime: no early exit while peer sends
}

// ---------------- emission: warp per packed row ----------------
__global__ void k_emission(const float* __restrict__ Wlin, const float* __restrict__ blin)
{
    int total = g_segoff[256];
    int gw   = (blockIdx.x * blockDim.x + threadIdx.x) >> 5;
    int nw   = (gridDim.x * blockDim.x) >> 5;
    int lane = threadIdx.x & 31;
    int k = lane & 15, half = lane >> 4;
    const float4* wr = (const float4*)(Wlin + k * 256 + half * 128);
    float4 wreg[32];
#pragma unroll
    for (int q = 0; q < 32; q++) wreg[q] = wr[q];
    float bk = blin[k];
    for (int r = gw; r < total; r += nw) {
        const float4* xr = (const float4*)(g_OUT2 + (size_t)r * 256 + half * 128);
        float a = 0.f;
#pragma unroll
        for (int q = 0; q < 32; q++) {
            float4 x = xr[q], wv = wreg[q];
            a = fmaf(x.x, wv.x, a); a = fmaf(x.y, wv.y, a);
            a = fmaf(x.z, wv.z, a); a = fmaf(x.w, wv.w, a);
        }
        a += __shfl_xor_sync(0xFFFFFFFFu, a, 16);
        if (lane < 16) g_EM[(size_t)r * 16 + k] = a + bk;
    }
}

// ---------------- Viterbi: one block per batch, smem history ----------------
__global__ __launch_bounds__(32, 1) void k_viterbi(
    const float* __restrict__ startv, const float* __restrict__ trans,
    const float* __restrict__ endv, float* __restrict__ out)
{
    __shared__ unsigned char hist[(TTOT - 1) * 16];
    int b    = blockIdx.x;
    int lane = threadIdx.x;
    int j    = lane & 15;
    int base = g_segoff[b * 8];
    int L    = g_segoff[b * 8 + 8] - base;
    float trC[16];
#pragma unroll
    for (int i = 0; i < 16; i++) trC[i] = trans[i * 16 + j];
    const float* em = g_EM + (size_t)base * 16;

    float sc  = startv[j] + em[j];
    float emj = em[16 + j];
    for (int t = 1; t < L; t++) {
        float em_next = (t + 1 < L) ? em[(t + 1) * 16 + j] : 0.0f;
        float best = -3.4e38f; int bi = 0;
#pragma unroll
        for (int i = 0; i < 16; i++) {
            float v = (__shfl_sync(0xFFFFFFFFu, sc, i) + trC[i]) + emj;
            if (v > best) { best = v; bi = i; }
        }
        sc = best;
        if (lane < 16) hist[(t - 1) * 16 + j] = (unsigned char)bi;
        emj = em_next;
    }
    float fin = sc + endv[j];
    float bestv = -3.4e38f; int last = 0;
#pragma unroll
    for (int i = 0; i < 16; i++) {
        float v = __shfl_sync(0xFFFFFFFFu, fin, i);
        if (v > bestv) { bestv = v; last = i; }
    }
    __syncwarp();
    if (lane == 0) {
        out[32768 + b] = bestv;
        int cur = last;
        out[(TTOT - 1) * 32 + b] = (float)cur;
        for (int t = TTOT - 1; t >= L; t--) out[(t - 1) * 32 + b] = (float)cur;
        for (int t = L - 1; t >= 1; t--) {
            cur = hist[(t - 1) * 16 + cur];
            out[(t - 1) * 32 + b] = (float)cur;
        }
    }
}

// ---------------- launch ----------------
extern "C" void kernel_launch(void* const* d_in, const int* in_sizes, int n_in,
                              void* d_out, int out_size)
{
    const int*   texts   = (const int*)  d_in[0];
    const int*   lengths = (const int*)  d_in[1];
    const float* emb     = (const float*)d_in[2];
    const float* Wih_f   = (const float*)d_in[3];
    const float* Whh_f   = (const float*)d_in[4];
    const float* bih_f   = (const float*)d_in[5];
    const float* bhh_f   = (const float*)d_in[6];
    const float* Wih_b   = (const float*)d_in[7];
    const float* Whh_b   = (const float*)d_in[8];
    const float* bih_b   = (const float*)d_in[9];
    const float* bhh_b   = (const float*)d_in[10];
    const float* Wlin    = (const float*)d_in[11];
    const float* blin    = (const float*)d_in[12];
    const float* crf_s   = (const float*)d_in[13];
    const float* crf_t   = (const float*)d_in[14];
    const float* crf_e   = (const float*)d_in[15];
    float* out = (float*)d_out;

    cudaFuncSetAttribute(k_lstm1, cudaFuncAttributeMaxDynamicSharedMemorySize, SMEM_LSTM);
    cudaFuncSetAttribute(k_gemm3<1>, cudaFuncAttributeMaxDynamicSharedMemorySize, SMEM_G3);
    cudaFuncSetAttribute(k_gemm3<0>, cudaFuncAttributeMaxDynamicSharedMemorySize, SMEM_G3);

    float *pG1, *pP2, *pG2;
    cudaGetSymbolAddress((void**)&pG1, g_G1);
    cudaGetSymbolAddress((void**)&pP2, g_P2);
    cudaGetSymbolAddress((void**)&pG2, g_G2);

    k_offsets<<<1, 32>>>(lengths);
    k_rowmap<<<256, 128>>>(texts, lengths);
    k_convW<<<256, 256>>>(Wih_f, Wih_b, bih_f, bhh_f, bih_b, bhh_b);
    k_gemm3<1><<<dim3(256, 8), 256, SMEM_G3>>>(emb, pG1);
    k_lstm1<<<512, 512, SMEM_LSTM>>>(lengths, Whh_f, Whh_b);
    k_gemm3<0><<<dim3(256, 8), 256, SMEM_G3>>>(pP2, pG2);
    k_lstm2c<<<128, 512>>>(Whh_f, Whh_b);
    k_emission<<<148, 256>>>(Wlin, blin);
    k_viterbi<<<32, 32>>>(crf_s, crf_t, crf_e, out);
}